// round 9
// baseline (speedup 1.0000x reference)
#include <cuda_runtime.h>
#include <cuda_fp16.h>

#define NN 2048
#define DD 64
#define BM 64
#define BN 32
#define NKT (NN / BN)
#define ATT_SCALE 0.125f

#define QSTR2 36
#define KSTR2 36
#define VSTR2 20
#define KBUFW (BN * KSTR2)     // 1152 words
#define VBUFW (DD * VSTR2)     // 1280 words
#define SMEM_WORDS (2 * KBUFW + 2 * VBUFW)   // 4864 words = 19456 B (Q stage 2304 fits)

__device__ __forceinline__ float tanh_fast(float x) {
    float y; asm("tanh.approx.f32 %0, %1;" : "=f"(y) : "f"(x));
    return y;
}
__device__ __forceinline__ unsigned h2(float lo, float hi) {
    __half2 t = __floats2half2_rn(lo, hi);
    return *reinterpret_cast<unsigned*>(&t);
}
__device__ __forceinline__ void mma16(float c[4], const unsigned a[4],
                                      unsigned b0, unsigned b1) {
    asm volatile(
        "mma.sync.aligned.m16n8k16.row.col.f32.f16.f16.f32 "
        "{%0,%1,%2,%3}, {%4,%5,%6,%7}, {%8,%9}, {%0,%1,%2,%3};"
        : "+f"(c[0]), "+f"(c[1]), "+f"(c[2]), "+f"(c[3])
        : "r"(a[0]), "r"(a[1]), "r"(a[2]), "r"(a[3]), "r"(b0), "r"(b1));
}

__global__ __launch_bounds__(128, 4)
void selfatt_h16q_kernel(const float* __restrict__ Q, const float* __restrict__ K,
                         const float* __restrict__ V, const unsigned int* __restrict__ M,
                         float* __restrict__ O)
{
    __shared__ __align__(16) unsigned smem[SMEM_WORDS];

    const int tid  = threadIdx.x;
    const int lane = tid & 31;
    const int w    = tid >> 5;      // 0..3
    const int lg   = lane >> 2;
    const int lt   = lane & 3;
    const int r0   = w * 16;        // warp's 16 S-rows (BM=64)

    const int bh = blockIdx.y;
    const int q0 = blockIdx.x * BM;

    const float* qb = Q + (size_t)bh * NN * DD;
    const float* kb = K + (size_t)bh * NN * DD;
    const float* vb = V + (size_t)bh * NN * DD;
    const unsigned int* mb = M + (size_t)bh * NN * NN;

    const int s_row = tid >> 3;     // 0..15 (K staging row; +16 on pass 2)
    const int s_dg  = tid & 7;
    const int v_d0  = w * 16;       // V staging: warp covers 16 d rows

    // ---- stage Q fp16 (64 rows), pull A-fragments ----
    #pragma unroll
    for (int pass = 0; pass < 4; pass++) {
        int r = pass * 16 + s_row;
        const float4* src = (const float4*)(qb + (size_t)(q0 + r) * DD + s_dg * 8);
        float4 t0 = src[0], t1 = src[1];
        *(uint4*)(smem + r * QSTR2 + s_dg * 4) =
            make_uint4(h2(t0.x, t0.y), h2(t0.z, t0.w), h2(t1.x, t1.y), h2(t1.z, t1.w));
    }
    __syncthreads();
    unsigned qa[4][4];
    #pragma unroll
    for (int kb16 = 0; kb16 < 4; kb16++) {
        const unsigned* p0 = smem + (r0 + lg) * QSTR2 + kb16 * 8;
        const unsigned* p8 = p0 + 8 * QSTR2;
        qa[kb16][0] = p0[lt];     qa[kb16][1] = p8[lt];
        qa[kb16][2] = p0[lt + 4]; qa[kb16][3] = p8[lt + 4];
    }
    __syncthreads();

    // ---- stage K(0)->buf0, K(1)->buf1, V(0)->Vbuf0 ----
    {
        #pragma unroll
        for (int t = 0; t < 2; t++)
            #pragma unroll
            for (int pass = 0; pass < 2; pass++) {
                int key = pass * 16 + s_row;
                const float4* ks = (const float4*)(kb + (size_t)(t * BN + key) * DD + s_dg * 8);
                float4 t0 = ks[0], t1 = ks[1];
                *(uint4*)(smem + t * KBUFW + key * KSTR2 + s_dg * 4) =
                    make_uint4(h2(t0.x, t0.y), h2(t0.z, t0.w), h2(t1.x, t1.y), h2(t1.z, t1.w));
            }
        // V: warp w covers d rows 16w..16w+15; lane = m
        const float4* vs = (const float4*)(vb + (size_t)lane * DD + v_d0);
        float f[16];
        *(float4*)&f[0] = vs[0]; *(float4*)&f[4]  = vs[1];
        *(float4*)&f[8] = vs[2]; *(float4*)&f[12] = vs[3];
        float g[16];
        #pragma unroll
        for (int j = 0; j < 16; j++) g[j] = __shfl_xor_sync(0xffffffffu, f[j], 1);
        unsigned* vbuf = smem + 2 * KBUFW;
        if (!(lane & 1)) {
            #pragma unroll
            for (int j = 0; j < 8; j++)
                vbuf[(v_d0 + j) * VSTR2 + (lane >> 1)] = h2(f[j], g[j]);
        } else {
            #pragma unroll
            for (int j = 8; j < 16; j++)
                vbuf[(v_d0 + j) * VSTR2 + (lane >> 1)] = h2(g[j], f[j]);
        }
    }

    const unsigned int* mrow0 = mb + (size_t)(q0 + r0 + lg) * NN + 2 * lt;
    const unsigned int* mrow8 = mrow0 + 8 * (size_t)NN;
    uint2 mk0[4], mk8[4];
    #pragma unroll
    for (int nt = 0; nt < 4; nt++) {
        mk0[nt] = *(const uint2*)(mrow0 + nt * 8);
        mk8[nt] = *(const uint2*)(mrow8 + nt * 8);
    }
    __syncthreads();

    float oacc[8][4];
    #pragma unroll
    for (int nt = 0; nt < 8; nt++)
        #pragma unroll
        for (int i = 0; i < 4; i++) oacc[nt][i] = 0.0f;

    // ---- pre-loop GEMM1(0) ----
    float sc[4][4];
    #pragma unroll
    for (int nt = 0; nt < 4; nt++)
        #pragma unroll
        for (int i = 0; i < 4; i++) sc[nt][i] = 0.0f;
    #pragma unroll
    for (int kb16 = 0; kb16 < 4; kb16++)
        #pragma unroll
        for (int nt = 0; nt < 4; nt++) {
            const unsigned* kr = smem + (nt * 8 + lg) * KSTR2 + kb16 * 8;
            mma16(sc[nt], qa[kb16], kr[lt], kr[lt + 4]);
        }
    __syncthreads();

    for (int it = 0; it < NKT; it++) {
        const bool hasN1 = (it + 1 < NKT);
        const bool hasN2 = (it + 2 < NKT);

        // ---- LDG prefetch: K(it+2) [2 halves], V(it+1), mask(it+1) ----
        float4 kf[4], vf[4];
        uint2 mn0[4], mn8[4];
        if (hasN2) {
            #pragma unroll
            for (int pass = 0; pass < 2; pass++) {
                const float4* ks = (const float4*)(kb +
                    (size_t)((it + 2) * BN + pass * 16 + s_row) * DD + s_dg * 8);
                kf[2 * pass] = ks[0]; kf[2 * pass + 1] = ks[1];
            }
        }
        if (hasN1) {
            const float4* vs = (const float4*)(vb + (size_t)((it + 1) * BN + lane) * DD + v_d0);
            vf[0] = vs[0]; vf[1] = vs[1]; vf[2] = vs[2]; vf[3] = vs[3];
            const int nb = (it + 1) * BN;
            #pragma unroll
            for (int nt = 0; nt < 4; nt++) {
                mn0[nt] = *(const uint2*)(mrow0 + nb + nt * 8);
                mn8[nt] = *(const uint2*)(mrow8 + nb + nt * 8);
            }
        }

        // ---- tanh + mask + pack S(it) ----
        unsigned aS[2][4];
        #pragma unroll
        for (int kb2 = 0; kb2 < 2; kb2++) {
            {
                const int nt = 2 * kb2;
                float w0 = mk0[nt].x ? 0.0f : tanh_fast(sc[nt][0] * ATT_SCALE);
                float w1 = mk0[nt].y ? 0.0f : tanh_fast(sc[nt][1] * ATT_SCALE);
                float w2 = mk8[nt].x ? 0.0f : tanh_fast(sc[nt][2] * ATT_SCALE);
                float w3 = mk8[nt].y ? 0.0f : tanh_fast(sc[nt][3] * ATT_SCALE);
                aS[kb2][0] = h2(w0, w1);
                aS[kb2][1] = h2(w2, w3);
            }
            {
                const int nt = 2 * kb2 + 1;
                float w0 = mk0[nt].x ? 0.0f : tanh_fast(sc[nt][0] * ATT_SCALE);
                float w1 = mk0[nt].y ? 0.0f : tanh_fast(sc[nt][1] * ATT_SCALE);
                float w2 = mk8[nt].x ? 0.0f : tanh_fast(sc[nt][2] * ATT_SCALE);
                float w3 = mk8[nt].y ? 0.0f : tanh_fast(sc[nt][3] * ATT_SCALE);
                aS[kb2][2] = h2(w0, w1);
                aS[kb2][3] = h2(w2, w3);
            }
        }

        // ---- GEMM1(it+1) refills sc (independent of GEMM2 below) ----
        if (hasN1) {
            #pragma unroll
            for (int nt = 0; nt < 4; nt++)
                #pragma unroll
                for (int i = 0; i < 4; i++) sc[nt][i] = 0.0f;
            const unsigned* Kp = smem + ((it + 1) & 1) * KBUFW;
            #pragma unroll
            for (int kb16 = 0; kb16 < 4; kb16++)
                #pragma unroll
                for (int nt = 0; nt < 4; nt++) {
                    const unsigned* kr = Kp + (nt * 8 + lg) * KSTR2 + kb16 * 8;
                    mma16(sc[nt], qa[kb16], kr[lt], kr[lt + 4]);
                }
        }

        // ---- GEMM2(it) ----
        {
            const unsigned* Vp = smem + 2 * KBUFW + (it & 1) * VBUFW;
            #pragma unroll
            for (int kb2 = 0; kb2 < 2; kb2++)
                #pragma unroll
                for (int nt = 0; nt < 8; nt++) {
                    const unsigned* vr = Vp + (nt * 8 + lg) * VSTR2 + kb2 * 8;
                    mma16(oacc[nt], aS[kb2], vr[lt], vr[lt + 4]);
                }
        }

        // ---- STS commits ----
        if (hasN2) {
            #pragma unroll
            for (int pass = 0; pass < 2; pass++)
                *(uint4*)(smem + (it & 1) * KBUFW + (pass * 16 + s_row) * KSTR2 + s_dg * 4) =
                    make_uint4(h2(kf[2 * pass].x, kf[2 * pass].y),
                               h2(kf[2 * pass].z, kf[2 * pass].w),
                               h2(kf[2 * pass + 1].x, kf[2 * pass + 1].y),
                               h2(kf[2 * pass + 1].z, kf[2 * pass + 1].w));
        }
        if (hasN1) {
            float f[16];
            *(float4*)&f[0] = vf[0]; *(float4*)&f[4]  = vf[1];
            *(float4*)&f[8] = vf[2]; *(float4*)&f[12] = vf[3];
            float g[16];
            #pragma unroll
            for (int j = 0; j < 16; j++) g[j] = __shfl_xor_sync(0xffffffffu, f[j], 1);
            unsigned* vn = smem + 2 * KBUFW + ((it + 1) & 1) * VBUFW;
            if (!(lane & 1)) {
                #pragma unroll
                for (int j = 0; j < 8; j++)
                    vn[(v_d0 + j) * VSTR2 + (lane >> 1)] = h2(f[j], g[j]);
            } else {
                #pragma unroll
                for (int j = 8; j < 16; j++)
                    vn[(v_d0 + j) * VSTR2 + (lane >> 1)] = h2(g[j], f[j]);
            }
            #pragma unroll
            for (int nt = 0; nt < 4; nt++) { mk0[nt] = mn0[nt]; mk8[nt] = mn8[nt]; }
        }
        __syncthreads();
    }

    // ---- epilogue ----
    #pragma unroll
    for (int nt = 0; nt < 8; nt++) {
        float* o0 = O + ((size_t)bh * NN + q0 + r0 + lg) * DD + nt * 8 + 2 * lt;
        *(float2*)o0            = make_float2(oacc[nt][0], oacc[nt][1]);
        *(float2*)(o0 + 8 * DD) = make_float2(oacc[nt][2], oacc[nt][3]);
    }
}

extern "C" void kernel_launch(void* const* d_in, const int* in_sizes, int n_in,
                              void* d_out, int out_size)
{
    const float* q = (const float*)d_in[0];
    const float* k = (const float*)d_in[1];
    const float* v = (const float*)d_in[2];
    const unsigned int* m = (const unsigned int*)d_in[3];
    float* o = (float*)d_out;

    dim3 grid(NN / BM, 32);   // 32 x 32 = 1024 CTAs
    selfatt_h16q_kernel<<<grid, 128>>>(q, k, v, m, o);
}

// round 10
// speedup vs baseline: 1.8773x; 1.8773x over previous
#include <cuda_runtime.h>
#include <cuda_fp16.h>

#define NN 2048
#define DD 64
#define BM 128
#define BN 32
#define NKT (NN / BN)
#define ATT_SCALE 0.125f

#define QSTR2 36               // Q stage words/row
#define KSTR2 36               // K tile words/key-row (144 B)
#define VSTR2 20               // V tile words/d-row (80 B)
#define KBUFW (BN * KSTR2)     // 1152 words
#define VBUFW (DD * VSTR2)     // 1280 words
#define SMEM_WORDS (2 * KBUFW + 2 * VBUFW)   // 19456 B

__device__ __forceinline__ float tanh_fast(float x) {
    float y; asm("tanh.approx.f32 %0, %1;" : "=f"(y) : "f"(x));
    return y;
}
__device__ __forceinline__ unsigned h2(float lo, float hi) {
    __half2 t = __floats2half2_rn(lo, hi);
    return *reinterpret_cast<unsigned*>(&t);
}
__device__ __forceinline__ void mma16(float c[4], const unsigned a[4],
                                      unsigned b0, unsigned b1) {
    asm volatile(
        "mma.sync.aligned.m16n8k16.row.col.f32.f16.f16.f32 "
        "{%0,%1,%2,%3}, {%4,%5,%6,%7}, {%8,%9}, {%0,%1,%2,%3};"
        : "+f"(c[0]), "+f"(c[1]), "+f"(c[2]), "+f"(c[3])
        : "r"(a[0]), "r"(a[1]), "r"(a[2]), "r"(a[3]), "r"(b0), "r"(b1));
}
__device__ __forceinline__ void ldsm4(unsigned& r0, unsigned& r1, unsigned& r2,
                                      unsigned& r3, unsigned saddr) {
    asm volatile("ldmatrix.sync.aligned.m8n8.x4.shared.b16 {%0,%1,%2,%3}, [%4];"
                 : "=r"(r0), "=r"(r1), "=r"(r2), "=r"(r3) : "r"(saddr));
}

__global__ __launch_bounds__(256, 2)
void selfatt_h16m_kernel(const float* __restrict__ Q, const float* __restrict__ K,
                         const float* __restrict__ V, const unsigned int* __restrict__ M,
                         float* __restrict__ O)
{
    __shared__ __align__(16) unsigned smem[SMEM_WORDS];

    const int tid  = threadIdx.x;
    const int lane = tid & 31;
    const int w    = tid >> 5;
    const int lg   = lane >> 2;
    const int lt   = lane & 3;
    const int r0   = w * 16;

    // LDSM lane decomposition
    const int ln    = lane & 7;        // row within 8x8 matrix
    const int qsel  = (lane >> 4) & 1; // matrix pair select (nt within pair)
    const int qhalf = (lane >> 3) & 1; // half select (b0 / b1 words)

    const unsigned sbase = (unsigned)__cvta_generic_to_shared(smem);
    // lane-constant byte offsets for LDSM addressing
    const unsigned g1base = (unsigned)((qsel * 8 + ln) * 144 + qhalf * 16);
    const unsigned g2base = (unsigned)((qsel * 8 + ln) * 80 + qhalf * 16);

    const int bh = blockIdx.y;
    const int q0 = blockIdx.x * BM;

    const float* qb = Q + (size_t)bh * NN * DD;
    const float* kb = K + (size_t)bh * NN * DD;
    const float* vb = V + (size_t)bh * NN * DD;
    const unsigned int* mb = M + (size_t)bh * NN * NN;

    const int s_row = tid >> 3;
    const int s_dg  = tid & 7;
    const int v_d0  = w * 8;

    // ---- stage Q fp16, pull A-fragments ----
    #pragma unroll
    for (int pass = 0; pass < 4; pass++) {
        int r = pass * 32 + s_row;
        const float4* src = (const float4*)(qb + (size_t)(q0 + r) * DD + s_dg * 8);
        float4 t0 = src[0], t1 = src[1];
        *(uint4*)(smem + r * QSTR2 + s_dg * 4) =
            make_uint4(h2(t0.x, t0.y), h2(t0.z, t0.w), h2(t1.x, t1.y), h2(t1.z, t1.w));
    }
    __syncthreads();
    unsigned qa[4][4];
    #pragma unroll
    for (int kb16 = 0; kb16 < 4; kb16++) {
        const unsigned* p0 = smem + (r0 + lg) * QSTR2 + kb16 * 8;
        const unsigned* p8 = p0 + 8 * QSTR2;
        qa[kb16][0] = p0[lt];     qa[kb16][1] = p8[lt];
        qa[kb16][2] = p0[lt + 4]; qa[kb16][3] = p8[lt + 4];
    }
    __syncthreads();

    // ---- stage K(0)->buf0, K(1)->buf1, V(0)->Vbuf0 ----
    {
        #pragma unroll
        for (int t = 0; t < 2; t++) {
            const float4* ks = (const float4*)(kb + (size_t)(t * BN + s_row) * DD + s_dg * 8);
            float4 t0 = ks[0], t1 = ks[1];
            *(uint4*)(smem + t * KBUFW + s_row * KSTR2 + s_dg * 4) =
                make_uint4(h2(t0.x, t0.y), h2(t0.z, t0.w), h2(t1.x, t1.y), h2(t1.z, t1.w));
        }
        const float4* vs = (const float4*)(vb + (size_t)lane * DD + v_d0);
        float4 a = vs[0], b = vs[1];
        float f[8] = {a.x, a.y, a.z, a.w, b.x, b.y, b.z, b.w};
        float g[8];
        #pragma unroll
        for (int j = 0; j < 8; j++) g[j] = __shfl_xor_sync(0xffffffffu, f[j], 1);
        unsigned* vbuf = smem + 2 * KBUFW;
        if (!(lane & 1)) {
            #pragma unroll
            for (int j = 0; j < 4; j++)
                vbuf[(v_d0 + j) * VSTR2 + (lane >> 1)] = h2(f[j], g[j]);
        } else {
            #pragma unroll
            for (int j = 4; j < 8; j++)
                vbuf[(v_d0 + j) * VSTR2 + (lane >> 1)] = h2(g[j], f[j]);
        }
    }

    const unsigned int* mrow0 = mb + (size_t)(q0 + r0 + lg) * NN + 2 * lt;
    const unsigned int* mrow8 = mrow0 + 8 * (size_t)NN;
    uint2 mk0[4], mk8[4];
    #pragma unroll
    for (int nt = 0; nt < 4; nt++) {
        mk0[nt] = *(const uint2*)(mrow0 + nt * 8);
        mk8[nt] = *(const uint2*)(mrow8 + nt * 8);
    }
    __syncthreads();

    float oacc[8][4];
    #pragma unroll
    for (int nt = 0; nt < 8; nt++)
        #pragma unroll
        for (int i = 0; i < 4; i++) oacc[nt][i] = 0.0f;

    // ---- pre-loop GEMM1(0) from Kbuf0 (LDSM) ----
    float sc[4][4];
    #pragma unroll
    for (int nt = 0; nt < 4; nt++)
        #pragma unroll
        for (int i = 0; i < 4; i++) sc[nt][i] = 0.0f;
    #pragma unroll
    for (int kb16 = 0; kb16 < 4; kb16++)
        #pragma unroll
        for (int ntp = 0; ntp < 2; ntp++) {
            unsigned b0, b1, b2, b3;
            ldsm4(b0, b1, b2, b3, sbase + g1base + ntp * 2304 + kb16 * 32);
            mma16(sc[ntp * 2 + 0], qa[kb16], b0, b1);
            mma16(sc[ntp * 2 + 1], qa[kb16], b2, b3);
        }
    __syncthreads();   // isolate GEMM1(0) reads from body-0 K stores

    for (int it = 0; it < NKT; it++) {
        const bool hasN1 = (it + 1 < NKT);
        const bool hasN2 = (it + 2 < NKT);

        // ---- LDG prefetch: K(it+2), V(it+1), mask(it+1) ----
        float4 kf0, kf1, vf0, vf1;
        uint2 mn0[4], mn8[4];
        if (hasN2) {
            const float4* ks = (const float4*)(kb + (size_t)((it + 2) * BN + s_row) * DD + s_dg * 8);
            kf0 = ks[0]; kf1 = ks[1];
        }
        if (hasN1) {
            const float4* vs = (const float4*)(vb + (size_t)((it + 1) * BN + lane) * DD + v_d0);
            vf0 = vs[0]; vf1 = vs[1];
            const int nb = (it + 1) * BN;
            #pragma unroll
            for (int nt = 0; nt < 4; nt++) {
                mn0[nt] = *(const uint2*)(mrow0 + nb + nt * 8);
                mn8[nt] = *(const uint2*)(mrow8 + nb + nt * 8);
            }
        }

        // ---- tanh + mask + pack S(it) ----
        unsigned aS[2][4];
        #pragma unroll
        for (int kb2 = 0; kb2 < 2; kb2++) {
            {
                const int nt = 2 * kb2;
                float w0 = mk0[nt].x ? 0.0f : tanh_fast(sc[nt][0] * ATT_SCALE);
                float w1 = mk0[nt].y ? 0.0f : tanh_fast(sc[nt][1] * ATT_SCALE);
                float w2 = mk8[nt].x ? 0.0f : tanh_fast(sc[nt][2] * ATT_SCALE);
                float w3 = mk8[nt].y ? 0.0f : tanh_fast(sc[nt][3] * ATT_SCALE);
                aS[kb2][0] = h2(w0, w1);
                aS[kb2][1] = h2(w2, w3);
            }
            {
                const int nt = 2 * kb2 + 1;
                float w0 = mk0[nt].x ? 0.0f : tanh_fast(sc[nt][0] * ATT_SCALE);
                float w1 = mk0[nt].y ? 0.0f : tanh_fast(sc[nt][1] * ATT_SCALE);
                float w2 = mk8[nt].x ? 0.0f : tanh_fast(sc[nt][2] * ATT_SCALE);
                float w3 = mk8[nt].y ? 0.0f : tanh_fast(sc[nt][3] * ATT_SCALE);
                aS[kb2][2] = h2(w0, w1);
                aS[kb2][3] = h2(w2, w3);
            }
        }

        // ---- GEMM1(it+1): refill sc from Kbuf (it+1)&1 via LDSM ----
        if (hasN1) {
            #pragma unroll
            for (int nt = 0; nt < 4; nt++)
                #pragma unroll
                for (int i = 0; i < 4; i++) sc[nt][i] = 0.0f;
            const unsigned kB = sbase + ((unsigned)((it + 1) & 1)) * (KBUFW * 4) + g1base;
            #pragma unroll
            for (int kb16 = 0; kb16 < 4; kb16++)
                #pragma unroll
                for (int ntp = 0; ntp < 2; ntp++) {
                    unsigned b0, b1, b2, b3;
                    ldsm4(b0, b1, b2, b3, kB + ntp * 2304 + kb16 * 32);
                    mma16(sc[ntp * 2 + 0], qa[kb16], b0, b1);
                    mma16(sc[ntp * 2 + 1], qa[kb16], b2, b3);
                }
        }

        // ---- GEMM2(it): oacc += S . V^T from Vbuf it&1 via LDSM ----
        {
            const unsigned vB = sbase + (unsigned)(2 * KBUFW * 4)
                              + ((unsigned)(it & 1)) * (VBUFW * 4) + g2base;
            #pragma unroll
            for (int kb2 = 0; kb2 < 2; kb2++)
                #pragma unroll
                for (int ntp = 0; ntp < 4; ntp++) {
                    unsigned b0, b1, b2, b3;
                    ldsm4(b0, b1, b2, b3, vB + ntp * 1280 + kb2 * 32);
                    mma16(oacc[ntp * 2 + 0], aS[kb2], b0, b1);
                    mma16(oacc[ntp * 2 + 1], aS[kb2], b2, b3);
                }
        }

        // ---- STS commits: K(it+2)->Kbuf it&1, V(it+1)->Vbuf (it+1)&1 ----
        if (hasN2) {
            *(uint4*)(smem + (it & 1) * KBUFW + s_row * KSTR2 + s_dg * 4) =
                make_uint4(h2(kf0.x, kf0.y), h2(kf0.z, kf0.w),
                           h2(kf1.x, kf1.y), h2(kf1.z, kf1.w));
        }
        if (hasN1) {
            float f[8] = {vf0.x, vf0.y, vf0.z, vf0.w, vf1.x, vf1.y, vf1.z, vf1.w};
            float g[8];
            #pragma unroll
            for (int j = 0; j < 8; j++) g[j] = __shfl_xor_sync(0xffffffffu, f[j], 1);
            unsigned* vn = smem + 2 * KBUFW + ((it + 1) & 1) * VBUFW;
            if (!(lane & 1)) {
                #pragma unroll
                for (int j = 0; j < 4; j++)
                    vn[(v_d0 + j) * VSTR2 + (lane >> 1)] = h2(f[j], g[j]);
            } else {
                #pragma unroll
                for (int j = 4; j < 8; j++)
                    vn[(v_d0 + j) * VSTR2 + (lane >> 1)] = h2(g[j], f[j]);
            }
            #pragma unroll
            for (int nt = 0; nt < 4; nt++) { mk0[nt] = mn0[nt]; mk8[nt] = mn8[nt]; }
        }
        __syncthreads();
    }

    // ---- epilogue ----
    #pragma unroll
    for (int nt = 0; nt < 8; nt++) {
        float* o0 = O + ((size_t)bh * NN + q0 + r0 + lg) * DD + nt * 8 + 2 * lt;
        *(float2*)o0            = make_float2(oacc[nt][0], oacc[nt][1]);
        *(float2*)(o0 + 8 * DD) = make_float2(oacc[nt][2], oacc[nt][3]);
    }
}

extern "C" void kernel_launch(void* const* d_in, const int* in_sizes, int n_in,
                              void* d_out, int out_size)
{
    const float* q = (const float*)d_in[0];
    const float* k = (const float*)d_in[1];
    const float* v = (const float*)d_in[2];
    const unsigned int* m = (const unsigned int*)d_in[3];
    float* o = (float*)d_out;

    dim3 grid(NN / BM, 32);   // 16 x 32 = 512 CTAs
    selfatt_h16m_kernel<<<grid, 256>>>(q, k, v, m, o);
}

// round 11
// speedup vs baseline: 2.9399x; 1.5660x over previous
#include <cuda_runtime.h>
#include <cuda_fp16.h>

#define NN 2048
#define DD 64
#define BM 128
#define BN 32
#define NKT (NN / BN)
#define ATT_SCALE 0.125f

#define QSTR2 36                 // words per row (144 B) — Q stage
#define TSTR  36                 // words per row (144 B) — K and V tiles
#define TBUFW (BN * TSTR)        // 1152 words per tile buffer
#define SMEM_WORDS (4 * TBUFW)   // K0,K1,V0,V1 = 18432 B (Q stage 4608 words fits)

__device__ __forceinline__ float tanh_fast(float x) {
    float y; asm("tanh.approx.f32 %0, %1;" : "=f"(y) : "f"(x));
    return y;
}
__device__ __forceinline__ unsigned h2(float lo, float hi) {
    __half2 t = __floats2half2_rn(lo, hi);
    return *reinterpret_cast<unsigned*>(&t);
}
// key permutation (involution): position p <-> key, swaps bit-fields [1:2] and [3:4]
__device__ __forceinline__ int prow(int r) {
    return (r & 1) | (((r >> 3) & 3) << 1) | (((r >> 1) & 3) << 3);
}
__device__ __forceinline__ void mma16(float c[4], const unsigned a[4],
                                      unsigned b0, unsigned b1) {
    asm volatile(
        "mma.sync.aligned.m16n8k16.row.col.f32.f16.f16.f32 "
        "{%0,%1,%2,%3}, {%4,%5,%6,%7}, {%8,%9}, {%0,%1,%2,%3};"
        : "+f"(c[0]), "+f"(c[1]), "+f"(c[2]), "+f"(c[3])
        : "r"(a[0]), "r"(a[1]), "r"(a[2]), "r"(a[3]), "r"(b0), "r"(b1));
}
__device__ __forceinline__ void ldsm4(unsigned& r0, unsigned& r1, unsigned& r2,
                                      unsigned& r3, unsigned saddr) {
    asm volatile("ldmatrix.sync.aligned.m8n8.x4.shared.b16 {%0,%1,%2,%3}, [%4];"
                 : "=r"(r0), "=r"(r1), "=r"(r2), "=r"(r3) : "r"(saddr));
}
__device__ __forceinline__ void ldsm4t(unsigned& r0, unsigned& r1, unsigned& r2,
                                       unsigned& r3, unsigned saddr) {
    asm volatile("ldmatrix.sync.aligned.m8n8.x4.trans.shared.b16 {%0,%1,%2,%3}, [%4];"
                 : "=r"(r0), "=r"(r1), "=r"(r2), "=r"(r3) : "r"(saddr));
}

__global__ __launch_bounds__(256, 2)
void selfatt_h16t_kernel(const float* __restrict__ Q, const float* __restrict__ K,
                         const float* __restrict__ V, const unsigned int* __restrict__ M,
                         float* __restrict__ O)
{
    __shared__ __align__(16) unsigned smem[SMEM_WORDS];

    const int tid  = threadIdx.x;
    const int lane = tid & 31;
    const int w    = tid >> 5;
    const int lg   = lane >> 2;
    const int lt   = lane & 3;
    const int r0   = w * 16;

    // LDSM lane-constant byte offsets (tile stride 144 B)
    const int ln    = lane & 7;
    const int qsel  = (lane >> 4) & 1;
    const int qhalf = (lane >> 3) & 1;
    const unsigned sbase  = (unsigned)__cvta_generic_to_shared(smem);
    const unsigned g1base = (unsigned)((qsel * 8 + ln) * 144 + qhalf * 16);        // K (non-trans)
    const unsigned g2base = (unsigned)((lane & 15) * 144 + ((lane >> 4) & 1) * 16); // V (trans)

    const int bh = blockIdx.y;
    const int q0 = blockIdx.x * BM;

    const float* qb = Q + (size_t)bh * NN * DD;
    const float* kb = K + (size_t)bh * NN * DD;
    const float* vb = V + (size_t)bh * NN * DD;
    const unsigned int* mb = M + (size_t)bh * NN * NN;

    const int s_row = tid >> 3;          // key within tile (GMEM row)
    const int s_dg  = tid & 7;           // 16B chunk within 128B row
    const int s_pr  = prow(s_row);       // permuted SMEM row position

    // ---- stage Q fp16, pull A-fragments ----
    #pragma unroll
    for (int pass = 0; pass < 4; pass++) {
        int r = pass * 32 + s_row;
        const float4* src = (const float4*)(qb + (size_t)(q0 + r) * DD + s_dg * 8);
        float4 t0 = src[0], t1 = src[1];
        *(uint4*)(smem + r * QSTR2 + s_dg * 4) =
            make_uint4(h2(t0.x, t0.y), h2(t0.z, t0.w), h2(t1.x, t1.y), h2(t1.z, t1.w));
    }
    __syncthreads();
    unsigned qa[4][4];
    #pragma unroll
    for (int kb16 = 0; kb16 < 4; kb16++) {
        const unsigned* p0 = smem + (r0 + lg) * QSTR2 + kb16 * 8;
        const unsigned* p8 = p0 + 8 * QSTR2;
        qa[kb16][0] = p0[lt];     qa[kb16][1] = p8[lt];
        qa[kb16][2] = p0[lt + 4]; qa[kb16][3] = p8[lt + 4];
    }
    __syncthreads();

    // ---- stage K(0)->Kbuf0, K(1)->Kbuf1, V(0)->Vbuf0 (all coalesced, permuted rows) ----
    {
        #pragma unroll
        for (int t = 0; t < 2; t++) {
            const float4* ks = (const float4*)(kb + (size_t)(t * BN + s_row) * DD + s_dg * 8);
            float4 t0 = ks[0], t1 = ks[1];
            *(uint4*)(smem + t * TBUFW + s_pr * TSTR + s_dg * 4) =
                make_uint4(h2(t0.x, t0.y), h2(t0.z, t0.w), h2(t1.x, t1.y), h2(t1.z, t1.w));
        }
        const float4* vs = (const float4*)(vb + (size_t)s_row * DD + s_dg * 8);
        float4 t0 = vs[0], t1 = vs[1];
        *(uint4*)(smem + 2 * TBUFW + s_pr * TSTR + s_dg * 4) =
            make_uint4(h2(t0.x, t0.y), h2(t0.z, t0.w), h2(t1.x, t1.y), h2(t1.z, t1.w));
    }

    // mask rows for this thread's fragments: rows (q0+r0+lg) and +8, keys 8*lt..8*lt+7
    const unsigned int* mrowA = mb + (size_t)(q0 + r0 + lg) * NN + 8 * lt;
    const unsigned int* mrowB = mrowA + 8 * (size_t)NN;
    unsigned mka[8], mkb[8];
    *(uint4*)&mka[0] = *(const uint4*)(mrowA);
    *(uint4*)&mka[4] = *(const uint4*)(mrowA + 4);
    *(uint4*)&mkb[0] = *(const uint4*)(mrowB);
    *(uint4*)&mkb[4] = *(const uint4*)(mrowB + 4);
    __syncthreads();

    float oacc[8][4];
    #pragma unroll
    for (int nt = 0; nt < 8; nt++)
        #pragma unroll
        for (int i = 0; i < 4; i++) oacc[nt][i] = 0.0f;

    // ---- pre-loop GEMM1(0) from Kbuf0 ----
    float sc[4][4];
    #pragma unroll
    for (int nt = 0; nt < 4; nt++)
        #pragma unroll
        for (int i = 0; i < 4; i++) sc[nt][i] = 0.0f;
    #pragma unroll
    for (int kb16 = 0; kb16 < 4; kb16++)
        #pragma unroll
        for (int ntp = 0; ntp < 2; ntp++) {
            unsigned b0, b1, b2, b3;
            ldsm4(b0, b1, b2, b3, sbase + g1base + ntp * 2304 + kb16 * 32);
            mma16(sc[ntp * 2 + 0], qa[kb16], b0, b1);
            mma16(sc[ntp * 2 + 1], qa[kb16], b2, b3);
        }
    __syncthreads();   // isolate GEMM1(0) reads from body-0 stores

    for (int it = 0; it < NKT; it++) {
        const bool hasN1 = (it + 1 < NKT);
        const bool hasN2 = (it + 2 < NKT);

        // ---- LDG prefetch: K(it+2), V(it+1) (coalesced), mask(it+1) (contiguous) ----
        float4 kf0, kf1, vf0, vf1;
        unsigned mna[8], mnb[8];
        if (hasN2) {
            const float4* ks = (const float4*)(kb + (size_t)((it + 2) * BN + s_row) * DD + s_dg * 8);
            kf0 = ks[0]; kf1 = ks[1];
        }
        if (hasN1) {
            const float4* vs = (const float4*)(vb + (size_t)((it + 1) * BN + s_row) * DD + s_dg * 8);
            vf0 = vs[0]; vf1 = vs[1];
            const int nb = (it + 1) * BN;
            *(uint4*)&mna[0] = *(const uint4*)(mrowA + nb);
            *(uint4*)&mna[4] = *(const uint4*)(mrowA + nb + 4);
            *(uint4*)&mnb[0] = *(const uint4*)(mrowB + nb);
            *(uint4*)&mnb[4] = *(const uint4*)(mrowB + nb + 4);
        }

        // ---- tanh + mask + pack S(it); fragment col c holds key 8lt+2nt+e = mk?[2nt+e] ----
        unsigned aS[2][4];
        #pragma unroll
        for (int kb2 = 0; kb2 < 2; kb2++) {
            {
                const int nt = 2 * kb2;
                float w0 = mka[2 * nt]     ? 0.0f : tanh_fast(sc[nt][0] * ATT_SCALE);
                float w1 = mka[2 * nt + 1] ? 0.0f : tanh_fast(sc[nt][1] * ATT_SCALE);
                float w2 = mkb[2 * nt]     ? 0.0f : tanh_fast(sc[nt][2] * ATT_SCALE);
                float w3 = mkb[2 * nt + 1] ? 0.0f : tanh_fast(sc[nt][3] * ATT_SCALE);
                aS[kb2][0] = h2(w0, w1);
                aS[kb2][1] = h2(w2, w3);
            }
            {
                const int nt = 2 * kb2 + 1;
                float w0 = mka[2 * nt]     ? 0.0f : tanh_fast(sc[nt][0] * ATT_SCALE);
                float w1 = mka[2 * nt + 1] ? 0.0f : tanh_fast(sc[nt][1] * ATT_SCALE);
                float w2 = mkb[2 * nt]     ? 0.0f : tanh_fast(sc[nt][2] * ATT_SCALE);
                float w3 = mkb[2 * nt + 1] ? 0.0f : tanh_fast(sc[nt][3] * ATT_SCALE);
                aS[kb2][2] = h2(w0, w1);
                aS[kb2][3] = h2(w2, w3);
            }
        }

        // ---- GEMM1(it+1): refill sc from Kbuf (it+1)&1 ----
        if (hasN1) {
            #pragma unroll
            for (int nt = 0; nt < 4; nt++)
                #pragma unroll
                for (int i = 0; i < 4; i++) sc[nt][i] = 0.0f;
            const unsigned kB = sbase + ((unsigned)((it + 1) & 1)) * (TBUFW * 4) + g1base;
            #pragma unroll
            for (int kb16 = 0; kb16 < 4; kb16++)
                #pragma unroll
                for (int ntp = 0; ntp < 2; ntp++) {
                    unsigned b0, b1, b2, b3;
                    ldsm4(b0, b1, b2, b3, kB + ntp * 2304 + kb16 * 32);
                    mma16(sc[ntp * 2 + 0], qa[kb16], b0, b1);
                    mma16(sc[ntp * 2 + 1], qa[kb16], b2, b3);
                }
        }

        // ---- GEMM2(it): oacc += S . V from Vbuf it&1 via ldmatrix.trans ----
        {
            const unsigned vB = sbase + (unsigned)(2 * TBUFW * 4)
                              + ((unsigned)(it & 1)) * (TBUFW * 4) + g2base;
            #pragma unroll
            for (int kb2 = 0; kb2 < 2; kb2++)
                #pragma unroll
                for (int ntp = 0; ntp < 4; ntp++) {
                    unsigned b0, b1, b2, b3;
                    ldsm4t(b0, b1, b2, b3, vB + kb2 * 2304 + ntp * 32);
                    mma16(oacc[ntp * 2 + 0], aS[kb2], b0, b1);
                    mma16(oacc[ntp * 2 + 1], aS[kb2], b2, b3);
                }
        }

        // ---- STS commits (coalesced, permuted rows) ----
        if (hasN2) {
            *(uint4*)(smem + (it & 1) * TBUFW + s_pr * TSTR + s_dg * 4) =
                make_uint4(h2(kf0.x, kf0.y), h2(kf0.z, kf0.w),
                           h2(kf1.x, kf1.y), h2(kf1.z, kf1.w));
        }
        if (hasN1) {
            *(uint4*)(smem + (2 + ((it + 1) & 1)) * TBUFW + s_pr * TSTR + s_dg * 4) =
                make_uint4(h2(vf0.x, vf0.y), h2(vf0.z, vf0.w),
                           h2(vf1.x, vf1.y), h2(vf1.z, vf1.w));
            #pragma unroll
            for (int j = 0; j < 8; j++) { mka[j] = mna[j]; mkb[j] = mnb[j]; }
        }
        __syncthreads();
    }

    // ---- epilogue ----
    #pragma unroll
    for (int nt = 0; nt < 8; nt++) {
        float* o0 = O + ((size_t)bh * NN + q0 + r0 + lg) * DD + nt * 8 + 2 * lt;
        *(float2*)o0            = make_float2(oacc[nt][0], oacc[nt][1]);
        *(float2*)(o0 + 8 * DD) = make_float2(oacc[nt][2], oacc[nt][3]);
    }
}

extern "C" void kernel_launch(void* const* d_in, const int* in_sizes, int n_in,
                              void* d_out, int out_size)
{
    const float* q = (const float*)d_in[0];
    const float* k = (const float*)d_in[1];
    const float* v = (const float*)d_in[2];
    const unsigned int* m = (const unsigned int*)d_in[3];
    float* o = (float*)d_out;

    dim3 grid(NN / BM, 32);   // 16 x 32 = 512 CTAs
    selfatt_h16t_kernel<<<grid, 256>>>(q, k, v, m, o);
}

// round 12
// speedup vs baseline: 3.4523x; 1.1743x over previous
#include <cuda_runtime.h>
#include <cuda_fp16.h>

#define NN 2048
#define DD 64
#define BH 32
#define BM 128
#define BN 32
#define NKT (NN / BN)
#define ATT_SCALE 0.125f

#define QSTR2 36                 // words per row (144 B) — Q stage
#define TSTR  36                 // words per row (144 B) — K and V tiles
#define TBUFW (BN * TSTR)        // 1152 words per tile buffer
#define SMEM_WORDS (4 * TBUFW)   // 18432 B (Q stage aliases this exactly)

#define TOTH (BH * NN * DD)      // 4,194,304 halfs per tensor

__device__ __align__(16) __half QH[TOTH];
__device__ __align__(16) __half KH[TOTH];
__device__ __align__(16) __half VH[TOTH];

__device__ __forceinline__ float tanh_fast(float x) {
    float y; asm("tanh.approx.f32 %0, %1;" : "=f"(y) : "f"(x));
    return y;
}
__device__ __forceinline__ unsigned h2(float lo, float hi) {
    __half2 t = __floats2half2_rn(lo, hi);
    return *reinterpret_cast<unsigned*>(&t);
}
// key permutation (involution) for conflict-free SMEM tiles
__device__ __forceinline__ int prow(int r) {
    return (r & 1) | (((r >> 3) & 3) << 1) | (((r >> 1) & 3) << 3);
}
__device__ __forceinline__ void mma16(float c[4], const unsigned a[4],
                                      unsigned b0, unsigned b1) {
    asm volatile(
        "mma.sync.aligned.m16n8k16.row.col.f32.f16.f16.f32 "
        "{%0,%1,%2,%3}, {%4,%5,%6,%7}, {%8,%9}, {%0,%1,%2,%3};"
        : "+f"(c[0]), "+f"(c[1]), "+f"(c[2]), "+f"(c[3])
        : "r"(a[0]), "r"(a[1]), "r"(a[2]), "r"(a[3]), "r"(b0), "r"(b1));
}
__device__ __forceinline__ void ldsm4(unsigned& r0, unsigned& r1, unsigned& r2,
                                      unsigned& r3, unsigned saddr) {
    asm volatile("ldmatrix.sync.aligned.m8n8.x4.shared.b16 {%0,%1,%2,%3}, [%4];"
                 : "=r"(r0), "=r"(r1), "=r"(r2), "=r"(r3) : "r"(saddr));
}
__device__ __forceinline__ void ldsm4t(unsigned& r0, unsigned& r1, unsigned& r2,
                                       unsigned& r3, unsigned saddr) {
    asm volatile("ldmatrix.sync.aligned.m8n8.x4.trans.shared.b16 {%0,%1,%2,%3}, [%4];"
                 : "=r"(r0), "=r"(r1), "=r"(r2), "=r"(r3) : "r"(saddr));
}
__device__ __forceinline__ void cpa16(unsigned dst, const void* src) {
    asm volatile("cp.async.cg.shared.global [%0], [%1], 16;" :: "r"(dst), "l"(src) : "memory");
}
#define CPA_COMMIT() asm volatile("cp.async.commit_group;" ::: "memory")
#define CPA_WAIT0()  asm volatile("cp.async.wait_group 0;" ::: "memory")

// shuffle-redistribute one uint4-worth of mask words from line-aligned loaders
__device__ __forceinline__ void mshuf(unsigned out[4], const uint4& a, const uint4& b,
                                      int src, bool pickb) {
    unsigned t0, t1;
    t0 = __shfl_sync(0xffffffffu, a.x, src); t1 = __shfl_sync(0xffffffffu, b.x, src);
    out[0] = pickb ? t1 : t0;
    t0 = __shfl_sync(0xffffffffu, a.y, src); t1 = __shfl_sync(0xffffffffu, b.y, src);
    out[1] = pickb ? t1 : t0;
    t0 = __shfl_sync(0xffffffffu, a.z, src); t1 = __shfl_sync(0xffffffffu, b.z, src);
    out[2] = pickb ? t1 : t0;
    t0 = __shfl_sync(0xffffffffu, a.w, src); t1 = __shfl_sync(0xffffffffu, b.w, src);
    out[3] = pickb ? t1 : t0;
}

// ---------------- prekernel: fp32 -> fp16 for Q, K, V ----------------
__global__ __launch_bounds__(256)
void cvt_f2h_kernel(const float* __restrict__ Q, const float* __restrict__ K,
                    const float* __restrict__ V)
{
    const int i = blockIdx.x * 256 + threadIdx.x;   // 0 .. TOTH/8-1
    {
        float4 a = ((const float4*)Q)[2 * i], b = ((const float4*)Q)[2 * i + 1];
        ((uint4*)QH)[i] = make_uint4(h2(a.x, a.y), h2(a.z, a.w), h2(b.x, b.y), h2(b.z, b.w));
    }
    {
        float4 a = ((const float4*)K)[2 * i], b = ((const float4*)K)[2 * i + 1];
        ((uint4*)KH)[i] = make_uint4(h2(a.x, a.y), h2(a.z, a.w), h2(b.x, b.y), h2(b.z, b.w));
    }
    {
        float4 a = ((const float4*)V)[2 * i], b = ((const float4*)V)[2 * i + 1];
        ((uint4*)VH)[i] = make_uint4(h2(a.x, a.y), h2(a.z, a.w), h2(b.x, b.y), h2(b.z, b.w));
    }
}

// ---------------- main kernel ----------------
__global__ __launch_bounds__(256, 2)
void selfatt_h16c_kernel(const unsigned int* __restrict__ M, float* __restrict__ O)
{
    __shared__ __align__(16) unsigned smem[SMEM_WORDS];

    const int tid  = threadIdx.x;
    const int lane = tid & 31;
    const int w    = tid >> 5;
    const int lg   = lane >> 2;
    const int lt   = lane & 3;
    const int r0   = w * 16;

    // LDSM lane-constant byte offsets (tile stride 144 B)
    const int ln    = lane & 7;
    const int qsel  = (lane >> 4) & 1;
    const int qhalf = (lane >> 3) & 1;
    const unsigned sbase  = (unsigned)__cvta_generic_to_shared(smem);
    const unsigned g1base = (unsigned)((qsel * 8 + ln) * 144 + qhalf * 16);         // K (non-trans)
    const unsigned g2base = (unsigned)((lane & 15) * 144 + ((lane >> 4) & 1) * 16); // V (trans)

    // mask shuffle sources
    const int sA0 = ((lg & 3) << 3) | (2 * lt);
    const int sA1 = sA0 + 1;
    const bool pkb = (lg & 4) != 0;

    const int bh = blockIdx.y;
    const int q0 = blockIdx.x * BM;

    const __half* qb = QH + (size_t)bh * NN * DD;
    const __half* kb = KH + (size_t)bh * NN * DD;
    const __half* vb = VH + (size_t)bh * NN * DD;
    const unsigned int* mb = M + (size_t)bh * NN * NN;

    const int s_row = tid >> 3;          // key within tile
    const int s_dg  = tid & 7;           // 16B chunk within 128B row
    const int s_pr  = prow(s_row);       // permuted SMEM row

    // per-thread cp.async SMEM destination offset within a tile buffer
    const unsigned t_dst = (unsigned)(s_pr * 144 + s_dg * 16);

    // ---- stage Q fp16 (direct copy), pull A-fragments ----
    #pragma unroll
    for (int pass = 0; pass < 4; pass++) {
        int r = pass * 32 + s_row;
        *(uint4*)(smem + r * QSTR2 + s_dg * 4) =
            *(const uint4*)(qb + (size_t)(q0 + r) * DD + s_dg * 8);
    }
    __syncthreads();
    unsigned qa[4][4];
    #pragma unroll
    for (int kb16 = 0; kb16 < 4; kb16++) {
        const unsigned* p0 = smem + (r0 + lg) * QSTR2 + kb16 * 8;
        const unsigned* p8 = p0 + 8 * QSTR2;
        qa[kb16][0] = p0[lt];     qa[kb16][1] = p8[lt];
        qa[kb16][2] = p0[lt + 4]; qa[kb16][3] = p8[lt + 4];
    }
    __syncthreads();   // Q stage dead -> tile buffers

    // ---- cp.async stage K(0)->Kbuf0, K(1)->Kbuf1, V(0)->Vbuf0 ----
    cpa16(sbase + 0 * (TBUFW * 4) + t_dst, kb + (size_t)s_row * DD + s_dg * 8);
    cpa16(sbase + 1 * (TBUFW * 4) + t_dst, kb + (size_t)(BN + s_row) * DD + s_dg * 8);
    cpa16(sbase + 2 * (TBUFW * 4) + t_dst, vb + (size_t)s_row * DD + s_dg * 8);
    CPA_COMMIT();

    // ---- mask tile 0: line-aligned raw loads + shuffle redistribute ----
    const unsigned int* mwbase = mb + (size_t)(q0 + r0) * NN;   // warp's 16 rows
    uint4 mr0, mr1, mr2, mr3;
    {
        const size_t rrow = (size_t)((lane >> 3)) * NN + 4 * (lane & 7);
        mr0 = *(const uint4*)(mwbase + rrow);
        mr1 = *(const uint4*)(mwbase + 4 * (size_t)NN + rrow);
        mr2 = *(const uint4*)(mwbase + 8 * (size_t)NN + rrow);
        mr3 = *(const uint4*)(mwbase + 12 * (size_t)NN + rrow);
    }
    unsigned mka[8], mkb[8];
    mshuf(&mka[0], mr0, mr1, sA0, pkb);
    mshuf(&mka[4], mr0, mr1, sA1, pkb);
    mshuf(&mkb[0], mr2, mr3, sA0, pkb);
    mshuf(&mkb[4], mr2, mr3, sA1, pkb);

    CPA_WAIT0();
    __syncthreads();

    float oacc[8][4];
    #pragma unroll
    for (int nt = 0; nt < 8; nt++)
        #pragma unroll
        for (int i = 0; i < 4; i++) oacc[nt][i] = 0.0f;

    // ---- pre-loop GEMM1(0) from Kbuf0 ----
    float sc[4][4];
    #pragma unroll
    for (int nt = 0; nt < 4; nt++)
        #pragma unroll
        for (int i = 0; i < 4; i++) sc[nt][i] = 0.0f;
    #pragma unroll
    for (int kb16 = 0; kb16 < 4; kb16++)
        #pragma unroll
        for (int ntp = 0; ntp < 2; ntp++) {
            unsigned b0, b1, b2, b3;
            ldsm4(b0, b1, b2, b3, sbase + g1base + ntp * 2304 + kb16 * 32);
            mma16(sc[ntp * 2 + 0], qa[kb16], b0, b1);
            mma16(sc[ntp * 2 + 1], qa[kb16], b2, b3);
        }
    __syncthreads();

    for (int it = 0; it < NKT; it++) {
        const bool hasN1 = (it + 1 < NKT);
        const bool hasN2 = (it + 2 < NKT);

        // ---- cp.async: K(it+2)->Kbuf[it&1], V(it+1)->Vbuf[(it+1)&1] ----
        if (hasN2)
            cpa16(sbase + (unsigned)((it & 1)) * (TBUFW * 4) + t_dst,
                  kb + (size_t)((it + 2) * BN + s_row) * DD + s_dg * 8);
        if (hasN1)
            cpa16(sbase + (unsigned)(2 + ((it + 1) & 1)) * (TBUFW * 4) + t_dst,
                  vb + (size_t)((it + 1) * BN + s_row) * DD + s_dg * 8);
        CPA_COMMIT();

        // ---- raw mask loads for tile it+1 (line-aligned) ----
        if (hasN1) {
            const size_t rrow = (size_t)((lane >> 3)) * NN + (it + 1) * BN + 4 * (lane & 7);
            mr0 = *(const uint4*)(mwbase + rrow);
            mr1 = *(const uint4*)(mwbase + 4 * (size_t)NN + rrow);
            mr2 = *(const uint4*)(mwbase + 8 * (size_t)NN + rrow);
            mr3 = *(const uint4*)(mwbase + 12 * (size_t)NN + rrow);
        }

        // ---- tanh + mask + pack S(it) ----
        unsigned aS[2][4];
        #pragma unroll
        for (int kb2 = 0; kb2 < 2; kb2++) {
            {
                const int nt = 2 * kb2;
                float w0 = mka[2 * nt]     ? 0.0f : tanh_fast(sc[nt][0] * ATT_SCALE);
                float w1 = mka[2 * nt + 1] ? 0.0f : tanh_fast(sc[nt][1] * ATT_SCALE);
                float w2 = mkb[2 * nt]     ? 0.0f : tanh_fast(sc[nt][2] * ATT_SCALE);
                float w3 = mkb[2 * nt + 1] ? 0.0f : tanh_fast(sc[nt][3] * ATT_SCALE);
                aS[kb2][0] = h2(w0, w1);
                aS[kb2][1] = h2(w2, w3);
            }
            {
                const int nt = 2 * kb2 + 1;
                float w0 = mka[2 * nt]     ? 0.0f : tanh_fast(sc[nt][0] * ATT_SCALE);
                float w1 = mka[2 * nt + 1] ? 0.0f : tanh_fast(sc[nt][1] * ATT_SCALE);
                float w2 = mkb[2 * nt]     ? 0.0f : tanh_fast(sc[nt][2] * ATT_SCALE);
                float w3 = mkb[2 * nt + 1] ? 0.0f : tanh_fast(sc[nt][3] * ATT_SCALE);
                aS[kb2][2] = h2(w0, w1);
                aS[kb2][3] = h2(w2, w3);
            }
        }

        // ---- GEMM1(it+1): refill sc from Kbuf (it+1)&1 ----
        if (hasN1) {
            #pragma unroll
            for (int nt = 0; nt < 4; nt++)
                #pragma unroll
                for (int i = 0; i < 4; i++) sc[nt][i] = 0.0f;
            const unsigned kB = sbase + ((unsigned)((it + 1) & 1)) * (TBUFW * 4) + g1base;
            #pragma unroll
            for (int kb16 = 0; kb16 < 4; kb16++)
                #pragma unroll
                for (int ntp = 0; ntp < 2; ntp++) {
                    unsigned b0, b1, b2, b3;
                    ldsm4(b0, b1, b2, b3, kB + ntp * 2304 + kb16 * 32);
                    mma16(sc[ntp * 2 + 0], qa[kb16], b0, b1);
                    mma16(sc[ntp * 2 + 1], qa[kb16], b2, b3);
                }
        }

        // ---- GEMM2(it): oacc += S . V from Vbuf it&1 ----
        {
            const unsigned vB = sbase + (unsigned)(2 * TBUFW * 4)
                              + ((unsigned)(it & 1)) * (TBUFW * 4) + g2base;
            #pragma unroll
            for (int kb2 = 0; kb2 < 2; kb2++)
                #pragma unroll
                for (int ntp = 0; ntp < 4; ntp++) {
                    unsigned b0, b1, b2, b3;
                    ldsm4t(b0, b1, b2, b3, vB + kb2 * 2304 + ntp * 32);
                    mma16(oacc[ntp * 2 + 0], aS[kb2], b0, b1);
                    mma16(oacc[ntp * 2 + 1], aS[kb2], b2, b3);
                }
        }

        // ---- redistribute next mask tile into mka/mkb ----
        if (hasN1) {
            mshuf(&mka[0], mr0, mr1, sA0, pkb);
            mshuf(&mka[4], mr0, mr1, sA1, pkb);
            mshuf(&mkb[0], mr2, mr3, sA0, pkb);
            mshuf(&mkb[4], mr2, mr3, sA1, pkb);
        }

        CPA_WAIT0();
        __syncthreads();
    }

    // ---- epilogue ----
    #pragma unroll
    for (int nt = 0; nt < 8; nt++) {
        float* o0 = O + ((size_t)bh * NN + q0 + r0 + lg) * DD + nt * 8 + 2 * lt;
        *(float2*)o0            = make_float2(oacc[nt][0], oacc[nt][1]);
        *(float2*)(o0 + 8 * DD) = make_float2(oacc[nt][2], oacc[nt][3]);
    }
}

extern "C" void kernel_launch(void* const* d_in, const int* in_sizes, int n_in,
                              void* d_out, int out_size)
{
    const float* q = (const float*)d_in[0];
    const float* k = (const float*)d_in[1];
    const float* v = (const float*)d_in[2];
    const unsigned int* m = (const unsigned int*)d_in[3];
    float* o = (float*)d_out;

    cvt_f2h_kernel<<<TOTH / 8 / 256, 256>>>(q, k, v);      // 2048 blocks
    dim3 grid(NN / BM, BH);                                 // 16 x 32
    selfatt_h16c_kernel<<<grid, 256>>>(m, o);
}